// round 16
// baseline (speedup 1.0000x reference)
#include <cuda_runtime.h>
#include <cuda_fp16.h>
#include <mma.h>
#include <math.h>

using namespace nvcuda;

#define SEQ   4096
#define DIM   512
#define BATCH 2
#define QSCALE 0.044194173824159216f  // 1/sqrt(512)

// ---------------- scratch (device globals; no allocations allowed) ----------
__device__ __half g_xh[BATCH * SEQ * DIM];     // fp16 x
__device__ __half g_Wh[4][DIM * DIM];          // fp16 Wq, Wk, Wv, Wo
__device__ __half g_Qh[BATCH * SEQ * DIM];
__device__ __half g_Kh[BATCH * SEQ * DIM];
__device__ __half g_Vh[BATCH * SEQ * DIM];
__device__ __half g_ATh[BATCH * SEQ * DIM];    // attn out, transposed, fp16

// ---------------- cache-policy load helpers ----------------------------------
__device__ __forceinline__ float4 ldg_evict_first_f4(const float* p) {
    float4 v;
    asm volatile("ld.global.L1::evict_first.v4.f32 {%0,%1,%2,%3}, [%4];"
                 : "=f"(v.x), "=f"(v.y), "=f"(v.z), "=f"(v.w) : "l"(p));
    return v;
}
__device__ __forceinline__ uint4 ldg_evict_last_u4(const __half* p) {
    uint4 v;
    asm volatile("ld.global.nc.L1::evict_last.v4.u32 {%0,%1,%2,%3}, [%4];"
                 : "=r"(v.x), "=r"(v.y), "=r"(v.z), "=r"(v.w) : "l"(p));
    return v;
}

// ---------------- fp32 -> fp16 converts --------------------------------------
__global__ __launch_bounds__(256) void convert_h_kernel(
    const float* __restrict__ in, __half* __restrict__ out)
{
    size_t i = ((size_t)blockIdx.x * 256 + threadIdx.x) * 4;
    float4 v = *(const float4*)(in + i);
    __half2 a = __float22half2_rn(make_float2(v.x, v.y));
    __half2 b = __float22half2_rn(make_float2(v.z, v.w));
    uint2 pk;
    pk.x = *(unsigned*)&a;
    pk.y = *(unsigned*)&b;
    *(uint2*)(out + i) = pk;
}

__global__ __launch_bounds__(256) void convert_w_kernel(
    const float* __restrict__ W0, const float* __restrict__ W1,
    const float* __restrict__ W2, const float* __restrict__ W3,
    __half* __restrict__ out)
{
    const float* src = (blockIdx.y == 0) ? W0 : (blockIdx.y == 1) ? W1
                     : (blockIdx.y == 2) ? W2 : W3;
    size_t i = ((size_t)blockIdx.x * 256 + threadIdx.x) * 4;
    float4 v = *(const float4*)(src + i);
    __half2 a = __float22half2_rn(make_float2(v.x, v.y));
    __half2 b = __float22half2_rn(make_float2(v.z, v.w));
    uint2 pk;
    pk.x = *(unsigned*)&a;
    pk.y = *(unsigned*)&b;
    *(uint2*)(out + (size_t)blockIdx.y * DIM * DIM + i) = pk;
}

__device__ __forceinline__ void cp16(void* s, const void* g) {
    unsigned a = (unsigned)__cvta_generic_to_shared(s);
    asm volatile("cp.async.cg.shared.global [%0], [%1], 16;\n" :: "r"(a), "l"(g));
}

// =============================================================================
// fp16 HMMA GEMM mainloop (unchanged R10-R13)
// =============================================================================
#define GH_SMEM 40960

#define GH_MAINLOOP(A_, W_)                                                     \
    extern __shared__ char dsm[];                                               \
    const int tid  = threadIdx.x;                                               \
    const int m0   = blockIdx.y * 128;                                          \
    const int n0   = blockIdx.x * 128;                                          \
    const int warp = tid >> 5;                                                  \
    const int wr   = warp >> 2;                                                 \
    const int wc   = warp & 3;                                                  \
    wmma::fragment<wmma::accumulator, 16, 16, 16, float> c[4][2];               \
    _Pragma("unroll")                                                           \
    for (int i = 0; i < 4; i++)                                                 \
        _Pragma("unroll")                                                       \
        for (int j = 0; j < 2; j++)                                             \
            wmma::fill_fragment(c[i][j], 0.0f);                                 \
    auto load_stage = [&](int s, int k0) {                                      \
        _Pragma("unroll")                                                       \
        for (int t = 0; t < 2; t++) {                                           \
            int id = tid + t * 256;                                             \
            int row = id >> 2, c8 = id & 3;                                     \
            cp16((__half*)(dsm + s * 10240) + row * 40 + c8 * 8,                \
                 &A_[(size_t)(m0 + row) * DIM + k0 + c8 * 8]);                  \
        }                                                                       \
        _Pragma("unroll")                                                       \
        for (int t = 0; t < 2; t++) {                                           \
            int id = tid + t * 256;                                             \
            int row = id >> 2, c8 = id & 3;                                     \
            cp16((__half*)(dsm + 20480 + s * 10240) + row * 40 + c8 * 8,        \
                 &W_[(size_t)(n0 + row) * DIM + k0 + c8 * 8]);                  \
        }                                                                       \
    };                                                                          \
    load_stage(0, 0);                                                           \
    asm volatile("cp.async.commit_group;\n");                                   \
    for (int s = 0; s < DIM / 32; s++) {                                        \
        const int cur = s & 1;                                                  \
        if (s + 1 < DIM / 32) {                                                 \
            load_stage(cur ^ 1, (s + 1) * 32);                                  \
            asm volatile("cp.async.commit_group;\n");                           \
            asm volatile("cp.async.wait_group 1;\n");                           \
        } else {                                                                \
            asm volatile("cp.async.wait_group 0;\n");                           \
        }                                                                       \
        __syncthreads();                                                        \
        _Pragma("unroll")                                                       \
        for (int kk = 0; kk < 32; kk += 16) {                                   \
            wmma::fragment<wmma::matrix_a, 16, 16, 16, __half, wmma::row_major> a[4]; \
            wmma::fragment<wmma::matrix_b, 16, 16, 16, __half, wmma::col_major> b[2]; \
            _Pragma("unroll")                                                   \
            for (int i = 0; i < 4; i++)                                         \
                wmma::load_matrix_sync(a[i],                                    \
                    (__half*)(dsm + cur * 10240) + (wr * 64 + i * 16) * 40 + kk, 40); \
            _Pragma("unroll")                                                   \
            for (int j = 0; j < 2; j++)                                         \
                wmma::load_matrix_sync(b[j],                                    \
                    (__half*)(dsm + 20480 + cur * 10240) + (wc * 32 + j * 16) * 40 + kk, 40); \
            _Pragma("unroll")                                                   \
            for (int i = 0; i < 4; i++)                                         \
                _Pragma("unroll")                                               \
                for (int j = 0; j < 2; j++)                                     \
                    wmma::mma_sync(c[i][j], a[i], b[j], c[i][j]);               \
        }                                                                       \
        __syncthreads();                                                        \
    }                                                                           \
    float* Cs = (float*)dsm;

// ---- QKV variant: fp16 output, no bias --------------------------------------
__global__ __launch_bounds__(256) void gemm_h_kernel(
    const __half* __restrict__ A,
    const __half* __restrict__ W0, const __half* __restrict__ W1, const __half* __restrict__ W2,
    __half* __restrict__ C0, __half* __restrict__ C1, __half* __restrict__ C2)
{
    const __half* W = (blockIdx.z == 0) ? W0 : (blockIdx.z == 1 ? W1 : W2);
    __half*       C = (blockIdx.z == 0) ? C0 : (blockIdx.z == 1 ? C1 : C2);
    GH_MAINLOOP(A, W)

    #pragma unroll
    for (int slab = 0; slab < 2; slab++) {
        if (wr == slab) {
            #pragma unroll
            for (int i = 0; i < 4; i++)
                #pragma unroll
                for (int j = 0; j < 2; j++)
                    wmma::store_matrix_sync(&Cs[(i * 16) * 128 + wc * 32 + j * 16],
                                            c[i][j], 128, wmma::mem_row_major);
        }
        __syncthreads();
        #pragma unroll
        for (int u = 0; u < 8; u++) {
            int g4 = tid + u * 256;
            int r  = g4 >> 5;
            int c4 = (g4 & 31) * 4;
            float4 v = *(float4*)&Cs[r * 128 + c4];
            __half2 h0 = __floats2half2_rn(v.x, v.y);
            __half2 h1 = __floats2half2_rn(v.z, v.w);
            uint2 pk;
            pk.x = *(unsigned*)&h0;
            pk.y = *(unsigned*)&h1;
            *(uint2*)&C[(size_t)(m0 + slab * 64 + r) * DIM + n0 + c4] = pk;
        }
        __syncthreads();
    }
}

// ---- O-proj variant: fp32 output + bias --------------------------------------
__global__ __launch_bounds__(256) void gemm_ho_kernel(
    const __half* __restrict__ A, const __half* __restrict__ W,
    const float* __restrict__ bias, float* __restrict__ C)
{
    GH_MAINLOOP(A, W)

    #pragma unroll
    for (int slab = 0; slab < 2; slab++) {
        if (wr == slab) {
            #pragma unroll
            for (int i = 0; i < 4; i++)
                #pragma unroll
                for (int j = 0; j < 2; j++)
                    wmma::store_matrix_sync(&Cs[(i * 16) * 128 + wc * 32 + j * 16],
                                            c[i][j], 128, wmma::mem_row_major);
        }
        __syncthreads();
        #pragma unroll
        for (int u = 0; u < 8; u++) {
            int g4 = tid + u * 256;
            int r  = g4 >> 5;
            int c4 = (g4 & 31) * 4;
            float4 v  = *(float4*)&Cs[r * 128 + c4];
            float4 bb = *(const float4*)&bias[n0 + c4];
            v.x += bb.x; v.y += bb.y; v.z += bb.z; v.w += bb.w;
            *(float4*)&C[(size_t)(m0 + slab * 64 + r) * DIM + n0 + c4] = v;
        }
        __syncthreads();
    }
}

// =============================================================================
// Sparse attention v6c: EXACT R13 structure (best known: 264us, 64 regs,
// occ 48%) + cache-policy hints:
//   mask  -> L1::evict_first (streaming, don't pollute L1)
//   K/V   -> ld.global.nc.L1::evict_last (persist for co-resident queries;
//            ~32 queries/SM traverse the same key windows in lockstep,
//            ~1.6 queries want each kept row)
// =============================================================================
__device__ __forceinline__ float dot16(uint4 a, uint4 b, const float* qr) {
    __half2 kh[8];
    *(uint4*)&kh[0] = a;
    *(uint4*)&kh[4] = b;
    float s = 0.0f;
    #pragma unroll
    for (int u = 0; u < 8; u++) {
        float2 kf = __half22float2(kh[u]);
        s += kf.x * qr[2 * u] + kf.y * qr[2 * u + 1];
    }
    return s;
}

__global__ __launch_bounds__(256) void attn_kernel(
    const __half* __restrict__ Q, const __half* __restrict__ K,
    const __half* __restrict__ V, const float* __restrict__ mask,
    const float* __restrict__ bq, const float* __restrict__ bv,
    __half* __restrict__ AT)
{
    __shared__ float accs[8][512];   // 16 KB
    __shared__ float lws[8];
    __shared__ int   wlist[8][128];  // 4 KB per-warp key lists

    const int tid  = threadIdx.x;
    const int warp = tid >> 5;
    const int lane = tid & 31;
    const int b    = blockIdx.x >> 12;
    const int q    = blockIdx.x & (SEQ - 1);

    const int d0 = lane * 8;
    const int d1 = 256 + lane * 8;

    // ---- q row into registers (dense layout)
    float qr[16];
    {
        const __half* qrow = Q + ((size_t)b * SEQ + q) * DIM;
        __half2 qh[8];
        *(uint4*)&qh[0] = *(const uint4*)(qrow + d0);
        *(uint4*)&qh[4] = *(const uint4*)(qrow + d1);
        float4 b0a = *(const float4*)(bq + d0);
        float4 b0b = *(const float4*)(bq + d0 + 4);
        float4 b1a = *(const float4*)(bq + d1);
        float4 b1b = *(const float4*)(bq + d1 + 4);
        float bb[16] = { b0a.x, b0a.y, b0a.z, b0a.w, b0b.x, b0b.y, b0b.z, b0b.w,
                         b1a.x, b1a.y, b1a.z, b1a.w, b1b.x, b1b.y, b1b.z, b1b.w };
        #pragma unroll
        for (int u = 0; u < 8; u++) {
            float2 h = __half22float2(qh[u]);
            qr[2 * u]     = (h.x + bb[2 * u])     * QSCALE;
            qr[2 * u + 1] = (h.y + bb[2 * u + 1]) * QSCALE;
        }
    }

    // ---- per-warp compaction: 4 float4-rounds over warp's 512 keys
    int cnt = 0;
    int* wl = wlist[warp];
    {
        const float* mrow = mask + ((size_t)b * SEQ + q) * SEQ;
        #pragma unroll
        for (int r = 0; r < 4; r++) {
            int base = warp * 512 + r * 128;
            float4 mc = ldg_evict_first_f4(&mrow[base + lane * 4]);
            #pragma unroll
            for (int t = 0; t < 4; t++) {
                float mval = (t == 0) ? mc.x : (t == 1) ? mc.y : (t == 2) ? mc.z : mc.w;
                bool keep = mval > 0.95f;
                unsigned bal = __ballot_sync(0xffffffffu, keep);
                if (keep) {
                    int pos = cnt + __popc(bal & ((1u << lane) - 1));
                    if (pos < 124) wl[pos] = base + lane * 4 + t;
                }
                cnt += __popc(bal);
            }
        }
        if (cnt > 124) cnt = 124;
        if (lane < 4) wl[cnt + lane] = wl[0];   // pad for int4 tail read
    }
    __syncwarp();

    float acc[16];
    #pragma unroll
    for (int i = 0; i < 16; i++) acc[i] = 0.0f;
    float lw = 0.0f;

    const __half* Kb = K + (size_t)b * SEQ * DIM;
    const __half* Vb = V + (size_t)b * SEQ * DIM;

    for (int i = 0; i < cnt; i += 4) {
        int4 kk = *(const int4*)&wl[i];   // broadcast LDS.128

        // ---- K loads (dense, evict_last, MLP 8)
        const __half* p0 = Kb + (size_t)kk.x * DIM;
        const __half* p1 = Kb + (size_t)kk.y * DIM;
        const __half* p2 = Kb + (size_t)kk.z * DIM;
        const __half* p3 = Kb + (size_t)kk.w * DIM;
        uint4 ka0 = ldg_evict_last_u4(p0 + d0), kb0 = ldg_evict_last_u4(p0 + d1);
        uint4 ka1 = ldg_evict_last_u4(p1 + d0), kb1 = ldg_evict_last_u4(p1 + d1);
        uint4 ka2 = ldg_evict_last_u4(p2 + d0), kb2 = ldg_evict_last_u4(p2 + d1);
        uint4 ka3 = ldg_evict_last_u4(p3 + d0), kb3 = ldg_evict_last_u4(p3 + d1);

        float s0 = dot16(ka0, kb0, qr);
        float s1 = dot16(ka1, kb1, qr);
        float s2 = dot16(ka2, kb2, qr);
        float s3 = dot16(ka3, kb3, qr);

        // ---- 4 independent butterflies (amortized latency)
        #pragma unroll
        for (int o = 16; o; o >>= 1) {
            s0 += __shfl_xor_sync(0xffffffffu, s0, o);
            s1 += __shfl_xor_sync(0xffffffffu, s1, o);
            s2 += __shfl_xor_sync(0xffffffffu, s2, o);
            s3 += __shfl_xor_sync(0xffffffffu, s3, o);
        }

        float pp0 = (i + 0 < cnt) ? __expf(s0) : 0.0f;
        float pp1 = (i + 1 < cnt) ? __expf(s1) : 0.0f;
        float pp2 = (i + 2 < cnt) ? __expf(s2) : 0.0f;
        float pp3 = (i + 3 < cnt) ? __expf(s3) : 0.0f;
        lw += pp0 + pp1 + pp2 + pp3;

        // ---- V loads (dense, evict_last) + accumulation
        const __half* v0 = Vb + (size_t)kk.x * DIM;
        const __half* v1 = Vb + (size_t)kk.y * DIM;
        const __half* v2 = Vb + (size_t)kk.z * DIM;
        const __half* v3 = Vb + (size_t)kk.w * DIM;
        uint4 va0 = ldg_evict_last_u4(v0 + d0), vb0 = ldg_evict_last_u4(v0 + d1);
        uint4 va1 = ldg_evict_last_u4(v1 + d0), vb1 = ldg_evict_last_u4(v1 + d1);
        uint4 va2 = ldg_evict_last_u4(v2 + d0), vb2 = ldg_evict_last_u4(v2 + d1);
        uint4 va3 = ldg_evict_last_u4(v3 + d0), vb3 = ldg_evict_last_u4(v3 + d1);

        __half2 vh[8];
        #pragma unroll
        for (int kset = 0; kset < 4; kset++) {
            float p = (kset == 0) ? pp0 : (kset == 1) ? pp1 : (kset == 2) ? pp2 : pp3;
            *(uint4*)&vh[0] = (kset == 0) ? va0 : (kset == 1) ? va1 : (kset == 2) ? va2 : va3;
            *(uint4*)&vh[4] = (kset == 0) ? vb0 : (kset == 1) ? vb1 : (kset == 2) ? vb2 : vb3;
            #pragma unroll
            for (int u = 0; u < 8; u++) {
                float2 vf = __half22float2(vh[u]);
                acc[2 * u]     += p * vf.x;
                acc[2 * u + 1] += p * vf.y;
            }
        }
    }

    // ---- cross-warp reduction (one-time)
    if (lane == 0) lws[warp] = lw;
    *(float4*)&accs[warp][d0]     = make_float4(acc[0], acc[1], acc[2],  acc[3]);
    *(float4*)&accs[warp][d0 + 4] = make_float4(acc[4], acc[5], acc[6],  acc[7]);
    *(float4*)&accs[warp][d1]     = make_float4(acc[8], acc[9], acc[10], acc[11]);
    *(float4*)&accs[warp][d1 + 4] = make_float4(acc[12], acc[13], acc[14], acc[15]);
    __syncthreads();

    float l = 0.0f;
    #pragma unroll
    for (int w = 0; w < 8; w++) l += lws[w];
    const float inv = 1.0f / l;

    #pragma unroll
    for (int t = 0; t < 2; t++) {
        int d = tid + t * 256;
        float o = 0.0f;
        #pragma unroll
        for (int w = 0; w < 8; w++) o += accs[w][d];
        AT[((size_t)b * DIM + d) * SEQ + q] = __float2half_rn(o * inv + bv[d]);
    }
}

// ---------------- launch ------------------------------------------------------
extern "C" void kernel_launch(void* const* d_in, const int* in_sizes, int n_in,
                              void* d_out, int out_size)
{
    const float* x    = (const float*)d_in[0];
    const float* mask = (const float*)d_in[1];
    const float* Wq   = (const float*)d_in[2];
    const float* bq   = (const float*)d_in[3];
    const float* Wk   = (const float*)d_in[4];
    // bk (d_in[5]) unused: softmax is shift-invariant in it
    const float* Wv   = (const float*)d_in[6];
    const float* bv   = (const float*)d_in[7];
    const float* Wo   = (const float*)d_in[8];
    const float* bo   = (const float*)d_in[9];

    __half *xh, *Wh, *Qh, *Kh, *Vh, *ATh;
    cudaGetSymbolAddress((void**)&xh,  g_xh);
    cudaGetSymbolAddress((void**)&Wh,  g_Wh);
    cudaGetSymbolAddress((void**)&Qh,  g_Qh);
    cudaGetSymbolAddress((void**)&Kh,  g_Kh);
    cudaGetSymbolAddress((void**)&Vh,  g_Vh);
    cudaGetSymbolAddress((void**)&ATh, g_ATh);

    // converts
    convert_h_kernel<<<(BATCH * SEQ * DIM / 4) / 256, 256>>>(x, xh);
    dim3 gw((DIM * DIM / 4) / 256, 4);
    convert_w_kernel<<<gw, 256>>>(Wq, Wk, Wv, Wo, Wh);

    // QKV projections via fp16 HMMA
    dim3 gq(DIM / 128, (BATCH * SEQ) / 128, 3);
    gemm_h_kernel<<<gq, 256, GH_SMEM>>>(xh, Wh, Wh + DIM * DIM, Wh + 2 * DIM * DIM,
                                        Qh, Kh, Vh);

    // fused sparse attention v6c (R13 structure + cache hints)
    attn_kernel<<<BATCH * SEQ, 256>>>(Qh, Kh, Vh, mask, bq, bv, ATh);

    // O-projection: fp16 HMMA, fp32 out + bo folded
    dim3 go(DIM / 128, (BATCH * SEQ) / 128, 1);
    gemm_ho_kernel<<<go, 256, GH_SMEM>>>(ATh, Wh + 3 * DIM * DIM, bo, (float*)d_out);
}

// round 17
// speedup vs baseline: 1.5842x; 1.5842x over previous
#include <cuda_runtime.h>
#include <cuda_fp16.h>
#include <mma.h>
#include <math.h>

using namespace nvcuda;

#define SEQ   4096
#define DIM   512
#define BATCH 2
#define QSCALE 0.044194173824159216f  // 1/sqrt(512)

// ---------------- scratch (device globals; no allocations allowed) ----------
__device__ __half g_xh[BATCH * SEQ * DIM];     // fp16 x
__device__ __half g_Wh[4][DIM * DIM];          // fp16 Wq, Wk, Wv, Wo
__device__ __half g_Qh[BATCH * SEQ * DIM];
__device__ __half g_Kh[BATCH * SEQ * DIM];
__device__ __half g_Vh[BATCH * SEQ * DIM];
__device__ __half g_ATh[BATCH * SEQ * DIM];    // attn out, transposed, fp16

// ---------------- fp32 -> fp16 converts --------------------------------------
__global__ __launch_bounds__(256) void convert_h_kernel(
    const float* __restrict__ in, __half* __restrict__ out)
{
    size_t i = ((size_t)blockIdx.x * 256 + threadIdx.x) * 4;
    float4 v = *(const float4*)(in + i);
    __half2 a = __float22half2_rn(make_float2(v.x, v.y));
    __half2 b = __float22half2_rn(make_float2(v.z, v.w));
    uint2 pk;
    pk.x = *(unsigned*)&a;
    pk.y = *(unsigned*)&b;
    *(uint2*)(out + i) = pk;
}

__global__ __launch_bounds__(256) void convert_w_kernel(
    const float* __restrict__ W0, const float* __restrict__ W1,
    const float* __restrict__ W2, const float* __restrict__ W3,
    __half* __restrict__ out)
{
    const float* src = (blockIdx.y == 0) ? W0 : (blockIdx.y == 1) ? W1
                     : (blockIdx.y == 2) ? W2 : W3;
    size_t i = ((size_t)blockIdx.x * 256 + threadIdx.x) * 4;
    float4 v = *(const float4*)(src + i);
    __half2 a = __float22half2_rn(make_float2(v.x, v.y));
    __half2 b = __float22half2_rn(make_float2(v.z, v.w));
    uint2 pk;
    pk.x = *(unsigned*)&a;
    pk.y = *(unsigned*)&b;
    *(uint2*)(out + (size_t)blockIdx.y * DIM * DIM + i) = pk;
}

__device__ __forceinline__ void cp16(void* s, const void* g) {
    unsigned a = (unsigned)__cvta_generic_to_shared(s);
    asm volatile("cp.async.cg.shared.global [%0], [%1], 16;\n" :: "r"(a), "l"(g));
}

// =============================================================================
// fp16 HMMA GEMM mainloop (unchanged R10-R13)
// =============================================================================
#define GH_SMEM 40960

#define GH_MAINLOOP(A_, W_)                                                     \
    extern __shared__ char dsm[];                                               \
    const int tid  = threadIdx.x;                                               \
    const int m0   = blockIdx.y * 128;                                          \
    const int n0   = blockIdx.x * 128;                                          \
    const int warp = tid >> 5;                                                  \
    const int wr   = warp >> 2;                                                 \
    const int wc   = warp & 3;                                                  \
    wmma::fragment<wmma::accumulator, 16, 16, 16, float> c[4][2];               \
    _Pragma("unroll")                                                           \
    for (int i = 0; i < 4; i++)                                                 \
        _Pragma("unroll")                                                       \
        for (int j = 0; j < 2; j++)                                             \
            wmma::fill_fragment(c[i][j], 0.0f);                                 \
    auto load_stage = [&](int s, int k0) {                                      \
        _Pragma("unroll")                                                       \
        for (int t = 0; t < 2; t++) {                                           \
            int id = tid + t * 256;                                             \
            int row = id >> 2, c8 = id & 3;                                     \
            cp16((__half*)(dsm + s * 10240) + row * 40 + c8 * 8,                \
                 &A_[(size_t)(m0 + row) * DIM + k0 + c8 * 8]);                  \
        }                                                                       \
        _Pragma("unroll")                                                       \
        for (int t = 0; t < 2; t++) {                                           \
            int id = tid + t * 256;                                             \
            int row = id >> 2, c8 = id & 3;                                     \
            cp16((__half*)(dsm + 20480 + s * 10240) + row * 40 + c8 * 8,        \
                 &W_[(size_t)(n0 + row) * DIM + k0 + c8 * 8]);                  \
        }                                                                       \
    };                                                                          \
    load_stage(0, 0);                                                           \
    asm volatile("cp.async.commit_group;\n");                                   \
    for (int s = 0; s < DIM / 32; s++) {                                        \
        const int cur = s & 1;                                                  \
        if (s + 1 < DIM / 32) {                                                 \
            load_stage(cur ^ 1, (s + 1) * 32);                                  \
            asm volatile("cp.async.commit_group;\n");                           \
            asm volatile("cp.async.wait_group 1;\n");                           \
        } else {                                                                \
            asm volatile("cp.async.wait_group 0;\n");                           \
        }                                                                       \
        __syncthreads();                                                        \
        _Pragma("unroll")                                                       \
        for (int kk = 0; kk < 32; kk += 16) {                                   \
            wmma::fragment<wmma::matrix_a, 16, 16, 16, __half, wmma::row_major> a[4]; \
            wmma::fragment<wmma::matrix_b, 16, 16, 16, __half, wmma::col_major> b[2]; \
            _Pragma("unroll")                                                   \
            for (int i = 0; i < 4; i++)                                         \
                wmma::load_matrix_sync(a[i],                                    \
                    (__half*)(dsm + cur * 10240) + (wr * 64 + i * 16) * 40 + kk, 40); \
            _Pragma("unroll")                                                   \
            for (int j = 0; j < 2; j++)                                         \
                wmma::load_matrix_sync(b[j],                                    \
                    (__half*)(dsm + 20480 + cur * 10240) + (wc * 32 + j * 16) * 40 + kk, 40); \
            _Pragma("unroll")                                                   \
            for (int i = 0; i < 4; i++)                                         \
                _Pragma("unroll")                                               \
                for (int j = 0; j < 2; j++)                                     \
                    wmma::mma_sync(c[i][j], a[i], b[j], c[i][j]);               \
        }                                                                       \
        __syncthreads();                                                        \
    }                                                                           \
    float* Cs = (float*)dsm;

// ---- QKV variant: fp16 output, no bias --------------------------------------
__global__ __launch_bounds__(256) void gemm_h_kernel(
    const __half* __restrict__ A,
    const __half* __restrict__ W0, const __half* __restrict__ W1, const __half* __restrict__ W2,
    __half* __restrict__ C0, __half* __restrict__ C1, __half* __restrict__ C2)
{
    const __half* W = (blockIdx.z == 0) ? W0 : (blockIdx.z == 1 ? W1 : W2);
    __half*       C = (blockIdx.z == 0) ? C0 : (blockIdx.z == 1 ? C1 : C2);
    GH_MAINLOOP(A, W)

    #pragma unroll
    for (int slab = 0; slab < 2; slab++) {
        if (wr == slab) {
            #pragma unroll
            for (int i = 0; i < 4; i++)
                #pragma unroll
                for (int j = 0; j < 2; j++)
                    wmma::store_matrix_sync(&Cs[(i * 16) * 128 + wc * 32 + j * 16],
                                            c[i][j], 128, wmma::mem_row_major);
        }
        __syncthreads();
        #pragma unroll
        for (int u = 0; u < 8; u++) {
            int g4 = tid + u * 256;
            int r  = g4 >> 5;
            int c4 = (g4 & 31) * 4;
            float4 v = *(float4*)&Cs[r * 128 + c4];
            __half2 h0 = __floats2half2_rn(v.x, v.y);
            __half2 h1 = __floats2half2_rn(v.z, v.w);
            uint2 pk;
            pk.x = *(unsigned*)&h0;
            pk.y = *(unsigned*)&h1;
            *(uint2*)&C[(size_t)(m0 + slab * 64 + r) * DIM + n0 + c4] = pk;
        }
        __syncthreads();
    }
}

// ---- O-proj variant: fp32 output + bias --------------------------------------
__global__ __launch_bounds__(256) void gemm_ho_kernel(
    const __half* __restrict__ A, const __half* __restrict__ W,
    const float* __restrict__ bias, float* __restrict__ C)
{
    GH_MAINLOOP(A, W)

    #pragma unroll
    for (int slab = 0; slab < 2; slab++) {
        if (wr == slab) {
            #pragma unroll
            for (int i = 0; i < 4; i++)
                #pragma unroll
                for (int j = 0; j < 2; j++)
                    wmma::store_matrix_sync(&Cs[(i * 16) * 128 + wc * 32 + j * 16],
                                            c[i][j], 128, wmma::mem_row_major);
        }
        __syncthreads();
        #pragma unroll
        for (int u = 0; u < 8; u++) {
            int g4 = tid + u * 256;
            int r  = g4 >> 5;
            int c4 = (g4 & 31) * 4;
            float4 v  = *(float4*)&Cs[r * 128 + c4];
            float4 bb = *(const float4*)&bias[n0 + c4];
            v.x += bb.x; v.y += bb.y; v.z += bb.z; v.w += bb.w;
            *(float4*)&C[(size_t)(m0 + slab * 64 + r) * DIM + n0 + c4] = v;
        }
        __syncthreads();
    }
}

// =============================================================================
// Sparse attention v6 (R13 exact — best measured: attn 264us, total 352.5us).
// Per-warp compaction + 4-key batching + dense lane mapping:
// lane owns dims [lane*8,+8) and [256+lane*8,+8) -> lane-dense LDG.128,
// 4 wavefronts per 512B instead of 8.
// =============================================================================
__device__ __forceinline__ float dot16(uint4 a, uint4 b, const float* qr) {
    __half2 kh[8];
    *(uint4*)&kh[0] = a;
    *(uint4*)&kh[4] = b;
    float s = 0.0f;
    #pragma unroll
    for (int u = 0; u < 8; u++) {
        float2 kf = __half22float2(kh[u]);
        s += kf.x * qr[2 * u] + kf.y * qr[2 * u + 1];
    }
    return s;
}

__global__ __launch_bounds__(256) void attn_kernel(
    const __half* __restrict__ Q, const __half* __restrict__ K,
    const __half* __restrict__ V, const float* __restrict__ mask,
    const float* __restrict__ bq, const float* __restrict__ bv,
    __half* __restrict__ AT)
{
    __shared__ float accs[8][512];   // 16 KB
    __shared__ float lws[8];
    __shared__ int   wlist[8][128];  // 4 KB per-warp key lists

    const int tid  = threadIdx.x;
    const int warp = tid >> 5;
    const int lane = tid & 31;
    const int b    = blockIdx.x >> 12;
    const int q    = blockIdx.x & (SEQ - 1);

    const int d0 = lane * 8;          // first dim block
    const int d1 = 256 + lane * 8;    // second dim block

    // ---- q row into registers (dense layout)
    float qr[16];
    {
        const __half* qrow = Q + ((size_t)b * SEQ + q) * DIM;
        __half2 qh[8];
        *(uint4*)&qh[0] = *(const uint4*)(qrow + d0);
        *(uint4*)&qh[4] = *(const uint4*)(qrow + d1);
        float4 b0a = *(const float4*)(bq + d0);
        float4 b0b = *(const float4*)(bq + d0 + 4);
        float4 b1a = *(const float4*)(bq + d1);
        float4 b1b = *(const float4*)(bq + d1 + 4);
        float bb[16] = { b0a.x, b0a.y, b0a.z, b0a.w, b0b.x, b0b.y, b0b.z, b0b.w,
                         b1a.x, b1a.y, b1a.z, b1a.w, b1b.x, b1b.y, b1b.z, b1b.w };
        #pragma unroll
        for (int u = 0; u < 8; u++) {
            float2 h = __half22float2(qh[u]);
            qr[2 * u]     = (h.x + bb[2 * u])     * QSCALE;
            qr[2 * u + 1] = (h.y + bb[2 * u + 1]) * QSCALE;
        }
    }

    // ---- per-warp compaction: 4 float4-rounds over warp's 512 keys
    int cnt = 0;
    int* wl = wlist[warp];
    {
        const float* mrow = mask + ((size_t)b * SEQ + q) * SEQ;
        #pragma unroll
        for (int r = 0; r < 4; r++) {
            int base = warp * 512 + r * 128;
            float4 mc = *(const float4*)&mrow[base + lane * 4];
            #pragma unroll
            for (int t = 0; t < 4; t++) {
                float mval = (t == 0) ? mc.x : (t == 1) ? mc.y : (t == 2) ? mc.z : mc.w;
                bool keep = mval > 0.95f;
                unsigned bal = __ballot_sync(0xffffffffu, keep);
                if (keep) {
                    int pos = cnt + __popc(bal & ((1u << lane) - 1));
                    if (pos < 124) wl[pos] = base + lane * 4 + t;
                }
                cnt += __popc(bal);
            }
        }
        if (cnt > 124) cnt = 124;
        if (lane < 4) wl[cnt + lane] = wl[0];   // pad for int4 tail read
    }
    __syncwarp();

    float acc[16];
    #pragma unroll
    for (int i = 0; i < 16; i++) acc[i] = 0.0f;
    float lw = 0.0f;

    const __half* Kb = K + (size_t)b * SEQ * DIM;
    const __half* Vb = V + (size_t)b * SEQ * DIM;

    for (int i = 0; i < cnt; i += 4) {
        int4 kk = *(const int4*)&wl[i];   // broadcast LDS.128

        // ---- K loads: 2 dense LDG.128 per row (4 wavefronts per 512B)
        const __half* p0 = Kb + (size_t)kk.x * DIM;
        const __half* p1 = Kb + (size_t)kk.y * DIM;
        const __half* p2 = Kb + (size_t)kk.z * DIM;
        const __half* p3 = Kb + (size_t)kk.w * DIM;
        uint4 ka0 = *(const uint4*)(p0 + d0), kb0 = *(const uint4*)(p0 + d1);
        uint4 ka1 = *(const uint4*)(p1 + d0), kb1 = *(const uint4*)(p1 + d1);
        uint4 ka2 = *(const uint4*)(p2 + d0), kb2 = *(const uint4*)(p2 + d1);
        uint4 ka3 = *(const uint4*)(p3 + d0), kb3 = *(const uint4*)(p3 + d1);

        float s0 = dot16(ka0, kb0, qr);
        float s1 = dot16(ka1, kb1, qr);
        float s2 = dot16(ka2, kb2, qr);
        float s3 = dot16(ka3, kb3, qr);

        // ---- 4 independent butterflies (amortized latency)
        #pragma unroll
        for (int o = 16; o; o >>= 1) {
            s0 += __shfl_xor_sync(0xffffffffu, s0, o);
            s1 += __shfl_xor_sync(0xffffffffu, s1, o);
            s2 += __shfl_xor_sync(0xffffffffu, s2, o);
            s3 += __shfl_xor_sync(0xffffffffu, s3, o);
        }

        float pp0 = (i + 0 < cnt) ? __expf(s0) : 0.0f;
        float pp1 = (i + 1 < cnt) ? __expf(s1) : 0.0f;
        float pp2 = (i + 2 < cnt) ? __expf(s2) : 0.0f;
        float pp3 = (i + 3 < cnt) ? __expf(s3) : 0.0f;
        lw += pp0 + pp1 + pp2 + pp3;

        // ---- V loads (dense) + accumulation
        const __half* v0 = Vb + (size_t)kk.x * DIM;
        const __half* v1 = Vb + (size_t)kk.y * DIM;
        const __half* v2 = Vb + (size_t)kk.z * DIM;
        const __half* v3 = Vb + (size_t)kk.w * DIM;
        uint4 va0 = *(const uint4*)(v0 + d0), vb0 = *(const uint4*)(v0 + d1);
        uint4 va1 = *(const uint4*)(v1 + d0), vb1 = *(const uint4*)(v1 + d1);
        uint4 va2 = *(const uint4*)(v2 + d0), vb2 = *(const uint4*)(v2 + d1);
        uint4 va3 = *(const uint4*)(v3 + d0), vb3 = *(const uint4*)(v3 + d1);

        __half2 vh[8];
        #pragma unroll
        for (int kset = 0; kset < 4; kset++) {
            float p = (kset == 0) ? pp0 : (kset == 1) ? pp1 : (kset == 2) ? pp2 : pp3;
            *(uint4*)&vh[0] = (kset == 0) ? va0 : (kset == 1) ? va1 : (kset == 2) ? va2 : va3;
            *(uint4*)&vh[4] = (kset == 0) ? vb0 : (kset == 1) ? vb1 : (kset == 2) ? vb2 : vb3;
            #pragma unroll
            for (int u = 0; u < 8; u++) {
                float2 vf = __half22float2(vh[u]);
                acc[2 * u]     += p * vf.x;
                acc[2 * u + 1] += p * vf.y;
            }
        }
    }

    // ---- cross-warp reduction (one-time)
    if (lane == 0) lws[warp] = lw;
    *(float4*)&accs[warp][d0]     = make_float4(acc[0], acc[1], acc[2],  acc[3]);
    *(float4*)&accs[warp][d0 + 4] = make_float4(acc[4], acc[5], acc[6],  acc[7]);
    *(float4*)&accs[warp][d1]     = make_float4(acc[8], acc[9], acc[10], acc[11]);
    *(float4*)&accs[warp][d1 + 4] = make_float4(acc[12], acc[13], acc[14], acc[15]);
    __syncthreads();

    float l = 0.0f;
    #pragma unroll
    for (int w = 0; w < 8; w++) l += lws[w];
    const float inv = 1.0f / l;

    #pragma unroll
    for (int t = 0; t < 2; t++) {
        int d = tid + t * 256;
        float o = 0.0f;
        #pragma unroll
        for (int w = 0; w < 8; w++) o += accs[w][d];
        AT[((size_t)b * DIM + d) * SEQ + q] = __float2half_rn(o * inv + bv[d]);
    }
}

// ---------------- launch ------------------------------------------------------
extern "C" void kernel_launch(void* const* d_in, const int* in_sizes, int n_in,
                              void* d_out, int out_size)
{
    const float* x    = (const float*)d_in[0];
    const float* mask = (const float*)d_in[1];
    const float* Wq   = (const float*)d_in[2];
    const float* bq   = (const float*)d_in[3];
    const float* Wk   = (const float*)d_in[4];
    // bk (d_in[5]) unused: softmax is shift-invariant in it
    const float* Wv   = (const float*)d_in[6];
    const float* bv   = (const float*)d_in[7];
    const float* Wo   = (const float*)d_in[8];
    const float* bo   = (const float*)d_in[9];

    __half *xh, *Wh, *Qh, *Kh, *Vh, *ATh;
    cudaGetSymbolAddress((void**)&xh,  g_xh);
    cudaGetSymbolAddress((void**)&Wh,  g_Wh);
    cudaGetSymbolAddress((void**)&Qh,  g_Qh);
    cudaGetSymbolAddress((void**)&Kh,  g_Kh);
    cudaGetSymbolAddress((void**)&Vh,  g_Vh);
    cudaGetSymbolAddress((void**)&ATh, g_ATh);

    // converts
    convert_h_kernel<<<(BATCH * SEQ * DIM / 4) / 256, 256>>>(x, xh);
    dim3 gw((DIM * DIM / 4) / 256, 4);
    convert_w_kernel<<<gw, 256>>>(Wq, Wk, Wv, Wo, Wh);

    // QKV projections via fp16 HMMA
    dim3 gq(DIM / 128, (BATCH * SEQ) / 128, 3);
    gemm_h_kernel<<<gq, 256, GH_SMEM>>>(xh, Wh, Wh + DIM * DIM, Wh + 2 * DIM * DIM,
                                        Qh, Kh, Vh);

    // fused sparse attention v6 (R13 exact)
    attn_kernel<<<BATCH * SEQ, 256>>>(Qh, Kh, Vh, mask, bq, bv, ATh);

    // O-projection: fp16 HMMA, fp32 out + bo folded
    dim3 go(DIM / 128, (BATCH * SEQ) / 128, 1);
    gemm_ho_kernel<<<go, 256, GH_SMEM>>>(ATh, Wh + 3 * DIM * DIM, bo, (float*)d_out);
}